// round 2
// baseline (speedup 1.0000x reference)
#include <cuda_runtime.h>
#include <cuda_bf16.h>

// SSIM, fused separable Gaussian conv (11x11, sigma=1.5), B=16,C=3,H=W=512.
// One block per 128x64 output tile. Per input row: stage img1/img2 row (+halo)
// to SMEM, horizontal 11-tap conv of 5 maps (mu1, mu2, E[x1^2], E[x2^2],
// E[x1 x2]) into a per-thread 11-deep register ring, vertical 11-tap conv from
// the ring, SSIM map value, block-reduce, atomicAdd(double), finalize = /N.

constexpr int IMG_H = 512;
constexpr int IMG_W = 512;
constexpr int N_IMG = 48;          // B*C = 16*3
constexpr int RAD   = 5;
constexpr int WS    = 11;
constexpr int TW    = 128;         // output tile width
constexpr int TH    = 64;          // output tile height
constexpr int COLS  = TW + 2 * RAD;   // 138 working columns
constexpr int ROWSIN = TH + 2 * RAD;  // 74 input rows actually needed
constexpr int ROWS_ITER = 77;         // 7 * 11, padded for clean phase unroll
constexpr int NTHREADS = 160;

constexpr float C1f = 0.01f * 0.01f;
constexpr float C2f = 0.03f * 0.03f;

// Normalized 1D Gaussian taps (sigma=1.5, ws=11), computed in double precision
// from exp(-(x-5)^2/4.5) / sum. Symmetric.
__device__ constexpr float GW[WS] = {
    0.00102838f, 0.00759876f, 0.03600078f, 0.10936070f, 0.21300554f,
    0.26601173f,
    0.21300554f, 0.10936070f, 0.03600078f, 0.00759876f, 0.00102838f
};

__device__ double g_accum;

__global__ void ssim_zero_kernel() { g_accum = 0.0; }

__global__ void __launch_bounds__(NTHREADS)
ssim_main_kernel(const float* __restrict__ img1, const float* __restrict__ img2)
{
    __shared__ float s1[COLS];
    __shared__ float s2[COLS];
    __shared__ float warp_sums[NTHREADS / 32];

    const int t  = threadIdx.x;
    const int x0 = blockIdx.x * TW;
    const int y0 = blockIdx.y * TH;
    const long imgOff = (long)blockIdx.z * (long)(IMG_H * IMG_W);
    const int wc = x0 - RAD + t;                 // working (global) column
    const bool colActive = (t < COLS);
    const bool colIn = colActive && ((unsigned)wc < (unsigned)IMG_W);

    const float* __restrict__ p1 = img1 + imgOff;
    const float* __restrict__ p2 = img2 + imgOff;

    float ring[WS][5];                           // horizontal conv results, 11 rows
    float acc = 0.0f;

    for (int base = 0; base < ROWS_ITER; base += WS) {
        #pragma unroll
        for (int ph = 0; ph < WS; ++ph) {
            const int ir = base + ph;            // row index within the tile sweep
            const int y  = y0 - RAD + ir;        // global input row (zero-padded)

            // ---- stage one input row (with zero padding) ----
            float v1 = 0.0f, v2 = 0.0f;
            if (colIn && ((unsigned)y < (unsigned)IMG_H) && (ir < ROWSIN)) {
                const int idx = y * IMG_W + wc;
                v1 = p1[idx];
                v2 = p2[idx];
            }
            __syncthreads();                     // previous row fully consumed
            if (colActive) { s1[t] = v1; s2[t] = v2; }
            __syncthreads();                     // row visible to all

            if (t < TW) {
                // ---- horizontal 11-tap conv of 5 maps (weights = immediates) ----
                float h0 = 0.f, h1 = 0.f, h2 = 0.f, h3 = 0.f, h4 = 0.f;
                #pragma unroll
                for (int k = 0; k < WS; ++k) {
                    const float a = s1[t + k];
                    const float b = s2[t + k];
                    const float w = GW[k];
                    h0 = fmaf(w, a,     h0);
                    h1 = fmaf(w, b,     h1);
                    h2 = fmaf(w, a * a, h2);
                    h3 = fmaf(w, b * b, h3);
                    h4 = fmaf(w, a * b, h4);
                }
                ring[ph][0] = h0; ring[ph][1] = h1; ring[ph][2] = h2;
                ring[ph][3] = h3; ring[ph][4] = h4;

                // ---- vertical 11-tap conv from register ring + SSIM ----
                if (ir >= WS - 1 && ir < ROWSIN) {
                    float m0 = 0.f, m1 = 0.f, m2 = 0.f, m3 = 0.f, m4 = 0.f;
                    #pragma unroll
                    for (int k = 0; k < WS; ++k) {
                        const int s = (ph + 1 + k) % WS;   // slot of row (ir-10+k)
                        const float w = GW[k];
                        m0 = fmaf(w, ring[s][0], m0);
                        m1 = fmaf(w, ring[s][1], m1);
                        m2 = fmaf(w, ring[s][2], m2);
                        m3 = fmaf(w, ring[s][3], m3);
                        m4 = fmaf(w, ring[s][4], m4);
                    }
                    const float m11 = m0 * m0;
                    const float m22 = m1 * m1;
                    const float m12 = m0 * m1;
                    const float sg1  = m2 - m11;
                    const float sg2  = m3 - m22;
                    const float sg12 = m4 - m12;
                    const float num = fmaf(2.f, m12,  C1f) * fmaf(2.f, sg12, C2f);
                    const float den = (m11 + m22 + C1f) * (sg1 + sg2 + C2f);
                    acc += __fdividef(num, den);
                }
            }
        }
    }

    // ---- block reduction ----
    #pragma unroll
    for (int o = 16; o > 0; o >>= 1)
        acc += __shfl_down_sync(0xffffffffu, acc, o);
    if ((t & 31) == 0) warp_sums[t >> 5] = acc;
    __syncthreads();
    if (t == 0) {
        float bs = 0.0f;
        #pragma unroll
        for (int wI = 0; wI < NTHREADS / 32; ++wI) bs += warp_sums[wI];
        atomicAdd(&g_accum, (double)bs);
    }
}

__global__ void ssim_final_kernel(float* __restrict__ out)
{
    out[0] = (float)(g_accum *
                     (1.0 / ((double)N_IMG * (double)IMG_H * (double)IMG_W)));
}

extern "C" void kernel_launch(void* const* d_in, const int* in_sizes, int n_in,
                              void* d_out, int out_size)
{
    const float* img1 = (const float*)d_in[0];
    const float* img2 = (const float*)d_in[1];
    // d_in[2] (window) unused: taps are baked in as immediates (same formula).
    float* out = (float*)d_out;

    ssim_zero_kernel<<<1, 1>>>();
    dim3 grid(IMG_W / TW, IMG_H / TH, N_IMG);   // 4 x 8 x 48 = 1536 blocks
    ssim_main_kernel<<<grid, NTHREADS>>>(img1, img2);
    ssim_final_kernel<<<1, 1>>>(out);
}

// round 3
// speedup vs baseline: 1.1287x; 1.1287x over previous
#include <cuda_runtime.h>

// SSIM via fused separable 11x11 Gaussian (sigma=1.5), B=16,C=3,H=W=512, fp32.
// One block per 128x64 output tile, 128 threads (one per output column).
// Rows swept in groups of 11: cp.async.cg 16B zero-fill copies stage a group
// into double-buffered SMEM while the previous group is convolved. Horizontal
// 11-tap conv of 5 maps -> per-thread 11-deep register ring -> vertical 11-tap
// conv -> SSIM map -> block reduce -> atomicAdd(double). Finalize divides and
// resets the accumulator (so no zeroing kernel is needed).

constexpr int IMG_H = 512;
constexpr int IMG_W = 512;
constexpr int N_IMG = 48;            // B*C
constexpr int RAD   = 5;
constexpr int WS    = 11;
constexpr int TW    = 128;           // output tile width == blockDim.x
constexpr int TH    = 64;            // output tile height
constexpr int LPAD  = 8;             // left halo, padded to 16B alignment
constexpr int COLS  = 144;           // LPAD + TW + 8 (>= 5 right halo), /4 ok
constexpr int ROWSIN = TH + 2 * RAD; // 74 input rows per tile
constexpr int NGROUP = 7;            // 7 * 11 = 77 rows swept (3 idle phases)
constexpr int NTHREADS = 128;
constexpr int F4_PER_ROW   = COLS / 4;          // 36
constexpr int F4_PER_GROUP = F4_PER_ROW * WS;   // 396

constexpr float C1f = 0.01f * 0.01f;
constexpr float C2f = 0.03f * 0.03f;

// Normalized 1D Gaussian taps (sigma=1.5, ws=11), symmetric; immediates in SASS.
__device__ constexpr float GW[WS] = {
    0.00102838f, 0.00759876f, 0.03600078f, 0.10936070f, 0.21300554f,
    0.26601173f,
    0.21300554f, 0.10936070f, 0.03600078f, 0.00759876f, 0.00102838f
};

__device__ double g_accum;   // zero-initialized at module load; reset by finalize

__device__ __forceinline__ void cpa16(void* smem_dst, const void* gmem_src, bool pred)
{
    unsigned s = (unsigned)__cvta_generic_to_shared(smem_dst);
    int n = pred ? 16 : 0;   // src-size 0 -> 16B of zeros, no memory access
    asm volatile("cp.async.cg.shared.global [%0], [%1], 16, %2;\n"
                 :: "r"(s), "l"(gmem_src), "r"(n));
}

__device__ __forceinline__ void issue_group(
    int g, int buf, int t, int x0, int y0,
    const float* __restrict__ p1, const float* __restrict__ p2,
    float (*s1)[WS][COLS], float (*s2)[WS][COLS])
{
    #pragma unroll
    for (int q = t; q < F4_PER_GROUP; q += NTHREADS) {
        const int r   = q / F4_PER_ROW;
        const int c4  = q - r * F4_PER_ROW;
        const int y   = y0 - RAD + g * WS + r;
        const int col = x0 - LPAD + c4 * 4;
        const bool ok = ((unsigned)y < (unsigned)IMG_H) &&
                        ((unsigned)col <= (unsigned)(IMG_W - 4));
        const long off = (long)y * IMG_W + col;
        cpa16(&s1[buf][r][c4 * 4], p1 + off, ok);
        cpa16(&s2[buf][r][c4 * 4], p2 + off, ok);
    }
}

__global__ void __launch_bounds__(NTHREADS)
ssim_main_kernel(const float* __restrict__ img1, const float* __restrict__ img2)
{
    __shared__ __align__(16) float s1[2][WS][COLS];
    __shared__ __align__(16) float s2[2][WS][COLS];
    __shared__ float warp_sums[NTHREADS / 32];

    const int t  = threadIdx.x;
    const int x0 = blockIdx.x * TW;
    const int y0 = blockIdx.y * TH;
    const long imgOff = (long)blockIdx.z * (long)(IMG_H * IMG_W);
    const float* __restrict__ p1 = img1 + imgOff;
    const float* __restrict__ p2 = img2 + imgOff;

    // Prologue: groups 0 and 1 in flight.
    issue_group(0, 0, t, x0, y0, p1, p2, s1, s2);
    asm volatile("cp.async.commit_group;\n");
    issue_group(1, 1, t, x0, y0, p1, p2, s1, s2);
    asm volatile("cp.async.commit_group;\n");

    float ring[WS][5];           // horizontal conv results for 11 rows
    float acc = 0.0f;

    for (int g = 0; g < NGROUP; ++g) {
        const int buf = g & 1;
        asm volatile("cp.async.wait_group 1;\n" ::: "memory");
        __syncthreads();                     // group g visible to all threads

        const float* __restrict__ r1 = &s1[buf][0][0];
        const float* __restrict__ r2 = &s2[buf][0][0];

        #pragma unroll
        for (int ph = 0; ph < WS; ++ph) {
            const int ir = g * WS + ph;      // row index within the sweep
            if (ir < ROWSIN) {
                // -- horizontal 11-tap conv of 5 maps (immediate weights) --
                float h0 = 0.f, h1 = 0.f, h2 = 0.f, h3 = 0.f, h4 = 0.f;
                #pragma unroll
                for (int k = 0; k < WS; ++k) {
                    const float a = r1[ph * COLS + t + 3 + k];
                    const float b = r2[ph * COLS + t + 3 + k];
                    const float w = GW[k];
                    h0 = fmaf(w, a,     h0);
                    h1 = fmaf(w, b,     h1);
                    h2 = fmaf(w, a * a, h2);
                    h3 = fmaf(w, b * b, h3);
                    h4 = fmaf(w, a * b, h4);
                }
                ring[ph][0] = h0; ring[ph][1] = h1; ring[ph][2] = h2;
                ring[ph][3] = h3; ring[ph][4] = h4;

                // -- vertical 11-tap conv from register ring + SSIM --
                if (ir >= WS - 1) {
                    float m0 = 0.f, m1 = 0.f, m2 = 0.f, m3 = 0.f, m4 = 0.f;
                    #pragma unroll
                    for (int k = 0; k < WS; ++k) {
                        const int s = (ph + 1 + k) % WS;   // slot of row ir-10+k
                        const float w = GW[k];
                        m0 = fmaf(w, ring[s][0], m0);
                        m1 = fmaf(w, ring[s][1], m1);
                        m2 = fmaf(w, ring[s][2], m2);
                        m3 = fmaf(w, ring[s][3], m3);
                        m4 = fmaf(w, ring[s][4], m4);
                    }
                    const float m11 = m0 * m0;
                    const float m22 = m1 * m1;
                    const float m12 = m0 * m1;
                    const float num = fmaf(2.f, m12,       C1f) *
                                      fmaf(2.f, m4 - m12,  C2f);
                    const float den = (m11 + m22 + C1f) *
                                      ((m2 - m11) + (m3 - m22) + C2f);
                    acc += __fdividef(num, den);
                }
            }
        }

        __syncthreads();                     // buffer fully consumed
        if (g + 2 < NGROUP)
            issue_group(g + 2, buf, t, x0, y0, p1, p2, s1, s2);
        asm volatile("cp.async.commit_group;\n");   // may be an empty group
    }

    // ---- block reduction ----
    #pragma unroll
    for (int o = 16; o > 0; o >>= 1)
        acc += __shfl_down_sync(0xffffffffu, acc, o);
    if ((t & 31) == 0) warp_sums[t >> 5] = acc;
    __syncthreads();
    if (t == 0) {
        float bs = 0.0f;
        #pragma unroll
        for (int w = 0; w < NTHREADS / 32; ++w) bs += warp_sums[w];
        atomicAdd(&g_accum, (double)bs);
    }
}

__global__ void ssim_final_kernel(float* __restrict__ out)
{
    out[0] = (float)(g_accum *
                     (1.0 / ((double)N_IMG * (double)IMG_H * (double)IMG_W)));
    g_accum = 0.0;   // ready for the next graph replay (deterministic)
}

extern "C" void kernel_launch(void* const* d_in, const int* in_sizes, int n_in,
                              void* d_out, int out_size)
{
    const float* img1 = (const float*)d_in[0];
    const float* img2 = (const float*)d_in[1];
    // d_in[2] (window) unused: taps are baked in as immediates (same formula).
    float* out = (float*)d_out;

    dim3 grid(IMG_W / TW, IMG_H / TH, N_IMG);   // 4 x 8 x 48 = 1536 blocks
    ssim_main_kernel<<<grid, NTHREADS>>>(img1, img2);
    ssim_final_kernel<<<1, 1>>>(out);
}

// round 4
// speedup vs baseline: 1.1329x; 1.0038x over previous
#include <cuda_runtime.h>

// SSIM, fused separable 11x11 Gaussian (sigma=1.5), B=16,C=3,H=W=512, fp32.
// Round-4: (a) 4-map s/d algebraic reformulation (s=a+b, d=a-b), (b) packed
// f32x2 math — each thread computes 2 adjacent output columns. 64 threads per
// 128x64 tile; cp.async double-buffered 11-row groups; in-place transform
// a,b -> s,d; horizontal conv -> packed 11-deep register ring -> vertical conv
// -> SSIM -> block reduce -> atomicAdd(double); finalize divides + resets.

using u64 = unsigned long long;

constexpr int IMG_H = 512;
constexpr int IMG_W = 512;
constexpr int N_IMG = 48;
constexpr int RAD   = 5;
constexpr int WS    = 11;
constexpr int TW    = 128;            // output tile width (2 cols per thread)
constexpr int TH    = 64;
constexpr int LPAD  = 8;
constexpr int COLS  = 144;            // LPAD + TW + 8
constexpr int ROWSIN = TH + 2 * RAD;  // 74
constexpr int NGROUP = 7;             // 7*11 = 77 rows swept
constexpr int NTHREADS = 64;
constexpr int F4_PER_ROW   = COLS / 4;          // 36
constexpr int F4_PER_GROUP = F4_PER_ROW * WS;   // 396

constexpr float C1f = 0.01f * 0.01f;
constexpr float C2f = 0.03f * 0.03f;

__device__ constexpr float GW[WS] = {
    0.00102838f, 0.00759876f, 0.03600078f, 0.10936070f, 0.21300554f,
    0.26601173f,
    0.21300554f, 0.10936070f, 0.03600078f, 0.00759876f, 0.00102838f
};

__device__ double g_accum;   // zero at load; reset by finalize each replay

// ---- packed f32x2 helpers (PTX-only on sm_10x) ----
__device__ __forceinline__ u64 pk2(float lo, float hi) {
    u64 r; asm("mov.b64 %0, {%1, %2};" : "=l"(r) : "f"(lo), "f"(hi)); return r;
}
__device__ __forceinline__ void upk2(u64 v, float& lo, float& hi) {
    asm("mov.b64 {%0, %1}, %2;" : "=f"(lo), "=f"(hi) : "l"(v));
}
__device__ __forceinline__ u64 fma2(u64 a, u64 b, u64 c) {
    u64 d; asm("fma.rn.f32x2 %0, %1, %2, %3;" : "=l"(d) : "l"(a), "l"(b), "l"(c)); return d;
}
__device__ __forceinline__ u64 mul2(u64 a, u64 b) {
    u64 d; asm("mul.rn.f32x2 %0, %1, %2;" : "=l"(d) : "l"(a), "l"(b)); return d;
}
__device__ __forceinline__ u64 add2(u64 a, u64 b) {
    u64 d; asm("add.rn.f32x2 %0, %1, %2;" : "=l"(d) : "l"(a), "l"(b)); return d;
}
__device__ __forceinline__ u64 sub2(u64 a, u64 b) {
    u64 d; asm("sub.rn.f32x2 %0, %1, %2;" : "=l"(d) : "l"(a), "l"(b)); return d;
}
// (hi of a, lo of b) -> pack   (odd->even straddle)
__device__ __forceinline__ u64 mid2(u64 a, u64 b) {
    float al, ah, bl, bh; upk2(a, al, ah); upk2(b, bl, bh); return pk2(ah, bl);
}

__device__ __forceinline__ void cpa16(void* smem_dst, const void* gmem_src, bool pred)
{
    unsigned s = (unsigned)__cvta_generic_to_shared(smem_dst);
    int n = pred ? 16 : 0;   // src-size 0 -> 16B zero-fill
    asm volatile("cp.async.cg.shared.global [%0], [%1], 16, %2;\n"
                 :: "r"(s), "l"(gmem_src), "r"(n));
}

__device__ __forceinline__ void issue_group(
    int g, int buf, int t, int x0, int y0,
    const float* __restrict__ p1, const float* __restrict__ p2,
    float (*s1)[WS][COLS], float (*s2)[WS][COLS])
{
    #pragma unroll
    for (int q = t; q < F4_PER_GROUP; q += NTHREADS) {
        const int r   = q / F4_PER_ROW;
        const int c4  = q - r * F4_PER_ROW;
        const int y   = y0 - RAD + g * WS + r;
        const int col = x0 - LPAD + c4 * 4;
        const bool ok = ((unsigned)y < (unsigned)IMG_H) &&
                        ((unsigned)col <= (unsigned)(IMG_W - 4));
        const long off = (long)y * IMG_W + col;
        cpa16(&s1[buf][r][c4 * 4], p1 + off, ok);
        cpa16(&s2[buf][r][c4 * 4], p2 + off, ok);
    }
}

__global__ void __launch_bounds__(NTHREADS)
ssim_main_kernel(const float* __restrict__ img1, const float* __restrict__ img2)
{
    __shared__ __align__(16) float s1[2][WS][COLS];
    __shared__ __align__(16) float s2[2][WS][COLS];
    __shared__ float warp_sums[NTHREADS / 32];

    const int t  = threadIdx.x;
    const int x0 = blockIdx.x * TW;
    const int y0 = blockIdx.y * TH;
    const long imgOff = (long)blockIdx.z * (long)(IMG_H * IMG_W);
    const float* __restrict__ p1 = img1 + imgOff;
    const float* __restrict__ p2 = img2 + imgOff;

    // Packed constants (kept in registers)
    u64 W2[WS];
    #pragma unroll
    for (int k = 0; k < WS; ++k) W2[k] = pk2(GW[k], GW[k]);
    const u64 HALF2 = pk2(0.5f, 0.5f);
    const u64 C1P   = pk2(C1f, C1f);
    const u64 C2P   = pk2(C2f, C2f);

    // Prologue: two groups in flight.
    issue_group(0, 0, t, x0, y0, p1, p2, s1, s2);
    asm volatile("cp.async.commit_group;\n");
    issue_group(1, 1, t, x0, y0, p1, p2, s1, s2);
    asm volatile("cp.async.commit_group;\n");

    u64 ring[WS][4];     // packed horizontal conv results (s, d, s^2, d^2)
    float accA = 0.0f, accB = 0.0f;

    for (int g = 0; g < NGROUP; ++g) {
        const int buf = g & 1;
        asm volatile("cp.async.wait_group 1;\n" ::: "memory");
        __syncthreads();                 // group g landed

        // ---- in-place transform a,b -> s=a+b, d=a-b (vectorized) ----
        {
            float4* a4 = reinterpret_cast<float4*>(&s1[buf][0][0]);
            float4* b4 = reinterpret_cast<float4*>(&s2[buf][0][0]);
            #pragma unroll
            for (int i = t; i < F4_PER_GROUP; i += NTHREADS) {
                const float4 a = a4[i];
                const float4 b = b4[i];
                float4 s, d;
                s.x = a.x + b.x; s.y = a.y + b.y; s.z = a.z + b.z; s.w = a.w + b.w;
                d.x = a.x - b.x; d.y = a.y - b.y; d.z = a.z - b.z; d.w = a.w - b.w;
                a4[i] = s; b4[i] = d;
            }
        }
        __syncthreads();                 // transformed rows visible

        #pragma unroll
        for (int ph = 0; ph < WS; ++ph) {
            const int ir = g * WS + ph;
            if (ir < ROWSIN) {
                // packed loads: local floats [2t+2 .. 2t+15] of s and d rows
                const u64* r1 = reinterpret_cast<const u64*>(&s1[buf][ph][2 * t + 2]);
                const u64* r2 = reinterpret_cast<const u64*>(&s2[buf][ph][2 * t + 2]);
                u64 ps[7], pd[7], qs[7], qd[7];
                #pragma unroll
                for (int j = 0; j < 7; ++j) {
                    ps[j] = r1[j];
                    pd[j] = r2[j];
                    qs[j] = mul2(ps[j], ps[j]);
                    qd[j] = mul2(pd[j], pd[j]);
                }

                // ---- horizontal 11-tap conv of 4 packed maps ----
                u64 hs = 0ull, hd = 0ull, hss = 0ull, hdd = 0ull;
                #pragma unroll
                for (int k = 0; k < WS; ++k) {
                    u64 vs, vd, vss, vdd;
                    if (k & 1) {
                        const int m = (k + 1) >> 1;      // 1..5
                        vs = ps[m]; vd = pd[m]; vss = qs[m]; vdd = qd[m];
                    } else {
                        const int m = k >> 1;            // 0..5
                        vs  = mid2(ps[m], ps[m + 1]);
                        vd  = mid2(pd[m], pd[m + 1]);
                        vss = mid2(qs[m], qs[m + 1]);
                        vdd = mid2(qd[m], qd[m + 1]);
                    }
                    hs  = fma2(W2[k], vs,  hs);
                    hd  = fma2(W2[k], vd,  hd);
                    hss = fma2(W2[k], vss, hss);
                    hdd = fma2(W2[k], vdd, hdd);
                }
                ring[ph][0] = hs;  ring[ph][1] = hd;
                ring[ph][2] = hss; ring[ph][3] = hdd;

                // ---- vertical 11-tap conv from packed ring + SSIM ----
                if (ir >= WS - 1) {
                    u64 m0 = 0ull, m1 = 0ull, m2 = 0ull, m3 = 0ull;
                    #pragma unroll
                    for (int k = 0; k < WS; ++k) {
                        const int s = (ph + 1 + k) % WS;
                        m0 = fma2(W2[k], ring[s][0], m0);
                        m1 = fma2(W2[k], ring[s][1], m1);
                        m2 = fma2(W2[k], ring[s][2], m2);
                        m3 = fma2(W2[k], ring[s][3], m3);
                    }
                    const u64 P  = mul2(m0, m0);         // (G*s)^2
                    const u64 Q  = mul2(m1, m1);         // (G*d)^2
                    const u64 SP = add2(P, Q);
                    const u64 SM = sub2(P, Q);
                    const u64 ES = add2(m2, m3);
                    const u64 ED = sub2(m2, m3);
                    const u64 n1 = fma2(SM, HALF2, C1P);             // 2mu1mu2+C1
                    const u64 n2 = fma2(sub2(ED, SM), HALF2, C2P);   // 2sig12+C2
                    const u64 d1 = fma2(SP, HALF2, C1P);             // mu1^2+mu2^2+C1
                    const u64 d2 = fma2(sub2(ES, SP), HALF2, C2P);   // sig1+sig2+C2
                    const u64 num = mul2(n1, n2);
                    const u64 den = mul2(d1, d2);
                    float nl, nh, dl, dh;
                    upk2(num, nl, nh);
                    upk2(den, dl, dh);
                    accA += __fdividef(nl, dl);
                    accB += __fdividef(nh, dh);
                }
            }
        }

        __syncthreads();                 // buffer consumed
        if (g + 2 < NGROUP)
            issue_group(g + 2, buf, t, x0, y0, p1, p2, s1, s2);
        asm volatile("cp.async.commit_group;\n");
    }

    // ---- block reduction ----
    float acc = accA + accB;
    #pragma unroll
    for (int o = 16; o > 0; o >>= 1)
        acc += __shfl_down_sync(0xffffffffu, acc, o);
    if ((t & 31) == 0) warp_sums[t >> 5] = acc;
    __syncthreads();
    if (t == 0) {
        float bs = 0.0f;
        #pragma unroll
        for (int w = 0; w < NTHREADS / 32; ++w) bs += warp_sums[w];
        atomicAdd(&g_accum, (double)bs);
    }
}

__global__ void ssim_final_kernel(float* __restrict__ out)
{
    out[0] = (float)(g_accum *
                     (1.0 / ((double)N_IMG * (double)IMG_H * (double)IMG_W)));
    g_accum = 0.0;
}

extern "C" void kernel_launch(void* const* d_in, const int* in_sizes, int n_in,
                              void* d_out, int out_size)
{
    const float* img1 = (const float*)d_in[0];
    const float* img2 = (const float*)d_in[1];
    float* out = (float*)d_out;

    dim3 grid(IMG_W / TW, IMG_H / TH, N_IMG);   // 4 x 8 x 48 = 1536 blocks
    ssim_main_kernel<<<grid, NTHREADS>>>(img1, img2);
    ssim_final_kernel<<<1, 1>>>(out);
}

// round 5
// speedup vs baseline: 1.2719x; 1.1227x over previous
#include <cuda_runtime.h>

// SSIM, fused separable 11x11 Gaussian (sigma=1.5), B=16,C=3,H=W=512, fp32.
// Round-5: single fused kernel (finalize via atomic ticket -> ncu profiles the
// real kernel). Scalar math with s/d reformulation (s=a+b, d=a-b -> only 4
// separable convs: G*s, G*d, G*s^2, G*d^2). 128 threads per 128x64 tile,
// cp.async double-buffered 11-row groups, per-thread 11-deep register ring,
// launch_bounds tuned for 5 blocks/SM (20 warps/SM) to cover latency.

constexpr int IMG_H = 512;
constexpr int IMG_W = 512;
constexpr int N_IMG = 48;
constexpr int RAD   = 5;
constexpr int WS    = 11;
constexpr int TW    = 128;
constexpr int TH    = 64;
constexpr int LPAD  = 8;
constexpr int COLS  = 144;            // LPAD + TW + 8
constexpr int ROWSIN = TH + 2 * RAD;  // 74
constexpr int NGROUP = 7;             // 7*11 = 77 rows swept
constexpr int NTHREADS = 128;
constexpr int F4_PER_ROW   = COLS / 4;          // 36
constexpr int F4_PER_GROUP = F4_PER_ROW * WS;   // 396
constexpr int NBLOCKS = (IMG_W / TW) * (IMG_H / TH) * N_IMG;   // 1536

constexpr float C1f = 0.01f * 0.01f;
constexpr float C2f = 0.03f * 0.03f;

__device__ constexpr float GW[WS] = {
    0.00102838f, 0.00759876f, 0.03600078f, 0.10936070f, 0.21300554f,
    0.26601173f,
    0.21300554f, 0.10936070f, 0.03600078f, 0.00759876f, 0.00102838f
};

__device__ double   g_accum;   // zero at module load; reset by last block
__device__ unsigned g_done;    // completion ticket; reset by last block

__device__ __forceinline__ void cpa16(void* smem_dst, const void* gmem_src, bool pred)
{
    unsigned s = (unsigned)__cvta_generic_to_shared(smem_dst);
    int n = pred ? 16 : 0;   // src-size 0 -> 16B zero-fill
    asm volatile("cp.async.cg.shared.global [%0], [%1], 16, %2;\n"
                 :: "r"(s), "l"(gmem_src), "r"(n));
}

__device__ __forceinline__ void issue_group(
    int g, int buf, int t, int x0, int y0,
    const float* __restrict__ p1, const float* __restrict__ p2,
    float (*s1)[WS][COLS], float (*s2)[WS][COLS])
{
    #pragma unroll
    for (int q = t; q < F4_PER_GROUP; q += NTHREADS) {
        const int r   = q / F4_PER_ROW;
        const int c4  = q - r * F4_PER_ROW;
        const int y   = y0 - RAD + g * WS + r;
        const int col = x0 - LPAD + c4 * 4;
        const bool ok = ((unsigned)y < (unsigned)IMG_H) &&
                        ((unsigned)col <= (unsigned)(IMG_W - 4));
        const long off = (long)y * IMG_W + col;
        cpa16(&s1[buf][r][c4 * 4], p1 + off, ok);
        cpa16(&s2[buf][r][c4 * 4], p2 + off, ok);
    }
}

__global__ void __launch_bounds__(NTHREADS, 5)
ssim_main_kernel(const float* __restrict__ img1, const float* __restrict__ img2,
                 float* __restrict__ out)
{
    __shared__ __align__(16) float s1[2][WS][COLS];   // s = a+b rows
    __shared__ __align__(16) float s2[2][WS][COLS];   // d = a-b rows
    __shared__ float warp_sums[NTHREADS / 32];

    const int t  = threadIdx.x;
    const int x0 = blockIdx.x * TW;
    const int y0 = blockIdx.y * TH;
    const long imgOff = (long)blockIdx.z * (long)(IMG_H * IMG_W);
    const float* __restrict__ p1 = img1 + imgOff;
    const float* __restrict__ p2 = img2 + imgOff;

    issue_group(0, 0, t, x0, y0, p1, p2, s1, s2);
    asm volatile("cp.async.commit_group;\n");
    issue_group(1, 1, t, x0, y0, p1, p2, s1, s2);
    asm volatile("cp.async.commit_group;\n");

    float ring[WS][4];     // horizontal conv results: G*s, G*d, G*s^2, G*d^2
    float acc = 0.0f;

    for (int g = 0; g < NGROUP; ++g) {
        const int buf = g & 1;
        asm volatile("cp.async.wait_group 1;\n" ::: "memory");
        __syncthreads();                 // group g landed (a,b raw rows)

        // ---- in-place transform a,b -> s=a+b, d=a-b (float4) ----
        {
            float4* a4 = reinterpret_cast<float4*>(&s1[buf][0][0]);
            float4* b4 = reinterpret_cast<float4*>(&s2[buf][0][0]);
            #pragma unroll
            for (int i = t; i < F4_PER_GROUP; i += NTHREADS) {
                const float4 a = a4[i];
                const float4 b = b4[i];
                float4 s, d;
                s.x = a.x + b.x; s.y = a.y + b.y; s.z = a.z + b.z; s.w = a.w + b.w;
                d.x = a.x - b.x; d.y = a.y - b.y; d.z = a.z - b.z; d.w = a.w - b.w;
                a4[i] = s; b4[i] = d;
            }
        }
        __syncthreads();                 // transformed rows visible

        #pragma unroll
        for (int ph = 0; ph < WS; ++ph) {
            const int ir = g * WS + ph;
            if (ir < ROWSIN) {
                const float* __restrict__ rs = &s1[buf][ph][t + 3];
                const float* __restrict__ rd = &s2[buf][ph][t + 3];

                // -- horizontal 11-tap conv of 4 maps (immediate weights) --
                float h0 = 0.f, h1 = 0.f, h2 = 0.f, h3 = 0.f;
                #pragma unroll
                for (int k = 0; k < WS; ++k) {
                    const float sv = rs[k];
                    const float dv = rd[k];
                    const float w  = GW[k];
                    h0 = fmaf(w, sv,      h0);
                    h1 = fmaf(w, dv,      h1);
                    h2 = fmaf(w, sv * sv, h2);
                    h3 = fmaf(w, dv * dv, h3);
                }
                ring[ph][0] = h0; ring[ph][1] = h1;
                ring[ph][2] = h2; ring[ph][3] = h3;

                // -- vertical 11-tap conv from register ring + SSIM --
                if (ir >= WS - 1) {
                    float m0 = 0.f, m1 = 0.f, m2 = 0.f, m3 = 0.f;
                    #pragma unroll
                    for (int k = 0; k < WS; ++k) {
                        const int s = (ph + 1 + k) % WS;
                        const float w = GW[k];
                        m0 = fmaf(w, ring[s][0], m0);
                        m1 = fmaf(w, ring[s][1], m1);
                        m2 = fmaf(w, ring[s][2], m2);
                        m3 = fmaf(w, ring[s][3], m3);
                    }
                    const float P  = m0 * m0;            // (G*s)^2
                    const float Q  = m1 * m1;            // (G*d)^2
                    const float SP = P + Q;              // 2(mu1^2+mu2^2)
                    const float SM = P - Q;              // 4 mu1 mu2
                    const float ES = m2 + m3;            // 2 E[x1^2+x2^2]
                    const float ED = m2 - m3;            // 4 E[x1 x2]
                    const float n1 = fmaf(SM, 0.5f, C1f);         // 2mu1mu2+C1
                    const float n2 = fmaf(ED - SM, 0.5f, C2f);    // 2sig12+C2
                    const float d1 = fmaf(SP, 0.5f, C1f);         // mu^2 sum+C1
                    const float d2 = fmaf(ES - SP, 0.5f, C2f);    // sig sum+C2
                    acc += __fdividef(n1 * n2, d1 * d2);
                }
            }
        }

        __syncthreads();                 // buffer consumed
        if (g + 2 < NGROUP)
            issue_group(g + 2, buf, t, x0, y0, p1, p2, s1, s2);
        asm volatile("cp.async.commit_group;\n");
    }

    // ---- block reduction ----
    #pragma unroll
    for (int o = 16; o > 0; o >>= 1)
        acc += __shfl_down_sync(0xffffffffu, acc, o);
    if ((t & 31) == 0) warp_sums[t >> 5] = acc;
    __syncthreads();

    // ---- global accumulate + fused finalize (last block) ----
    if (t == 0) {
        float bs = 0.0f;
        #pragma unroll
        for (int w = 0; w < NTHREADS / 32; ++w) bs += warp_sums[w];
        atomicAdd(&g_accum, (double)bs);
        __threadfence();
        const unsigned ticket = atomicAdd(&g_done, 1u);
        if (ticket == NBLOCKS - 1) {
            __threadfence();
            out[0] = (float)(g_accum *
                     (1.0 / ((double)N_IMG * (double)IMG_H * (double)IMG_W)));
            g_accum = 0.0;               // ready for next graph replay
            g_done  = 0u;
        }
    }
}

extern "C" void kernel_launch(void* const* d_in, const int* in_sizes, int n_in,
                              void* d_out, int out_size)
{
    const float* img1 = (const float*)d_in[0];
    const float* img2 = (const float*)d_in[1];
    float* out = (float*)d_out;

    dim3 grid(IMG_W / TW, IMG_H / TH, N_IMG);   // 4 x 8 x 48 = 1536 blocks
    ssim_main_kernel<<<grid, NTHREADS>>>(img1, img2, out);
}